// round 16
// baseline (speedup 1.0000x reference)
#include <cuda_runtime.h>
#include <cstdint>

#define FDIM 128
#define CDIM 132
#define KBE  136          // padded K (storage slots)
#define WRS  136          // W smem row stride in floats
#define TILE 128
#define NTHR 128

// smem byte offsets (per block)
#define SM_BS   0                           // bias: 136 floats
#define SM_B1S  1024                        // b1 double buffer: 2 x 2048
#define SM_DC   5120                        // d_chi double buffer: 2 x 4096 (128 rows x 32B)
#define SM_W    13312                       // W^T tf32 (f32): 136 x 136 x 4 = 73984
#define SMEM_BYTES (SM_W + KBE * WRS * 4)   // 87296 (x2 blocks/SM = 174592)

static __device__ __forceinline__ uint32_t tf(float v) {
    uint32_t r; asm("cvt.rna.tf32.f32 %0, %1;" : "=r"(r) : "f"(v)); return r;
}
static __device__ __forceinline__ void mma_t(float* c, const uint32_t* A,
                                             uint32_t b0, uint32_t b1) {
    asm volatile("mma.sync.aligned.m16n8k8.row.col.f32.tf32.tf32.f32 "
        "{%0,%1,%2,%3}, {%4,%5,%6,%7}, {%8,%9}, {%0,%1,%2,%3};"
        : "+f"(c[0]), "+f"(c[1]), "+f"(c[2]), "+f"(c[3])
        : "r"(A[0]), "r"(A[1]), "r"(A[2]), "r"(A[3]), "r"(b0), "r"(b1));
}

struct ARow { const float* p[8]; };  // clamped row pointers (+4*qc)

// One pair of k8 steps (s2 = 0..7 covers logical k [16*s2, 16*s2+16)).
// A: one float4 per row (k-permuted contiguity). B: LDS.64 from tf32 W smem.
template<int NG>
static __device__ __forceinline__ void k2step(
    int s2, const ARow& ar, const char* wB, float (*acc)[4])
{
    const int xo = s2 * 16;
    float4 v0[4], v1[4];
    #pragma unroll
    for (int f = 0; f < 4; ++f) {
        v0[f] = *(const float4*)(ar.p[2*f]   + xo);
        v1[f] = *(const float4*)(ar.p[2*f+1] + xo);
    }
    uint32_t A0[4][4], A1[4][4];
    #pragma unroll
    for (int f = 0; f < 4; ++f) {
        A0[f][0] = tf(v0[f].x); A0[f][1] = tf(v1[f].x);
        A0[f][2] = tf(v0[f].y); A0[f][3] = tf(v1[f].y);
        A1[f][0] = tf(v0[f].z); A1[f][1] = tf(v1[f].z);
        A1[f][2] = tf(v0[f].w); A1[f][3] = tf(v1[f].w);
    }
    #pragma unroll
    for (int g = 0; g < NG; ++g) {
        uint2 be = *(const uint2*)(wB + g * 4352 + s2 * 64);
        #pragma unroll
        for (int f = 0; f < 4; ++f)
            mma_t(acc[f * NG + g], A0[f], be.x, be.y);
        uint2 bo = *(const uint2*)(wB + g * 4352 + s2 * 64 + 32);
        #pragma unroll
        for (int f = 0; f < 4; ++f)
            mma_t(acc[f * NG + g], A1[f], bo.x, bo.y);
    }
}

template<int CW>
static __device__ __forceinline__ void compute_tile(
    const ARow& ar, const float* dc, const char* wB,
    const float* bs, float* b1s,
    float* __restrict__ a1, long long row0, long long n,
    int mrow, int qr, int qc)
{
    constexpr int NG = CW ? 8 : 9;
    constexpr int G0 = CW ? 9 : 0;

    float acc[4 * NG][4];
    #pragma unroll
    for (int i = 0; i < 4 * NG; ++i)
        #pragma unroll
        for (int j = 0; j < 4; ++j) acc[i][j] = 0.f;

    #pragma unroll
    for (int s2 = 0; s2 < 8; ++s2)
        k2step<NG>(s2, ar, wB, acc);

    // ---- k8 tail: logical k = 128..135, A from d_chi smem ----
    {
        uint32_t At[4][4];
        #pragma unroll
        for (int f = 0; f < 4; ++f) {
            int r = mrow + f * 16 + qr;
            float2 u0 = *(const float2*)(dc + r * 8 + 2 * qc);
            float2 u1 = *(const float2*)(dc + (r + 8) * 8 + 2 * qc);
            At[f][0] = tf(u0.x); At[f][1] = tf(u1.x);
            At[f][2] = tf(u0.y); At[f][3] = tf(u1.y);
        }
        #pragma unroll
        for (int g = 0; g < NG; ++g) {
            uint2 bt = *(const uint2*)(wB + g * 4352 + 128 * 4);
            #pragma unroll
            for (int f = 0; f < 4; ++f)
                mma_t(acc[f * NG + g], At[f], bt.x, bt.y);
        }
    }

    // ---- epilogue ----
    #pragma unroll
    for (int f = 0; f < 4; ++f) {
        #pragma unroll
        for (int g = 0; g < NG; ++g) {
            const int ga = G0 + g;
            const float* ac = acc[f * NG + g];
            const int colg = ga * 8 + qc * 2;
            if (ga < 16) {
                float bx = bs[colg], by = bs[colg + 1];
                long long r1 = row0 + mrow + f * 16 + qr;
                if (r1 < n)
                    *(float2*)(a1 + r1 * FDIM + colg) = make_float2(ac[0] + bx, ac[1] + by);
                if (r1 + 8 < n)
                    *(float2*)(a1 + (r1 + 8) * FDIM + colg) = make_float2(ac[2] + bx, ac[3] + by);
            } else if (ga == 16) {
                if (qc < 2) {
                    int l = qc * 2;
                    float bx = bs[FDIM + l], by = bs[FDIM + l + 1];
                    int rl = mrow + f * 16 + qr;
                    b1s[rl * 4 + l]       = ac[0] + bx;
                    b1s[rl * 4 + l + 1]   = ac[1] + by;
                    b1s[(rl + 8) * 4 + l]     = ac[2] + bx;
                    b1s[(rl + 8) * 4 + l + 1] = ac[3] + by;
                }
            }
        }
    }
}

// ---- d_chi staging: interleaved [s0,0,s1,0,s2,0,s3,0]; thread tid = row ----
static __device__ __forceinline__ void stage_dchi(
    const float* __restrict__ chi, char* sm, uint32_t dcoff,
    long long row, bool ok, int rloc)
{
    float c[16];
    #pragma unroll
    for (int q = 0; q < 4; ++q) {
        float4 v = ok ? *(const float4*)(chi + row * 16 + q * 4)
                      : make_float4(0.f, 0.f, 0.f, 0.f);
        c[q*4+0] = v.x; c[q*4+1] = v.y; c[q*4+2] = v.z; c[q*4+3] = v.w;
    }
    float s0 = c[0] * c[0];
    float s1 = c[1]*c[1] + c[2]*c[2] + c[3]*c[3];
    float s2 = 0.f, s3 = 0.f;
    #pragma unroll
    for (int m = 4; m < 9; ++m)  s2 += c[m] * c[m];
    #pragma unroll
    for (int m = 9; m < 16; ++m) s3 += c[m] * c[m];
    float* dc = (float*)(sm + dcoff);
    *(float4*)(dc + rloc * 8)     = make_float4(s0, 0.f, s1, 0.f);
    *(float4*)(dc + rloc * 8 + 4) = make_float4(s2, 0.f, s3, 0.f);
}

// ---- chi_out: thread tid = row; reloads chi (L2-warm) ----
static __device__ __forceinline__ void chi_out_store(
    float* __restrict__ co, const float* __restrict__ chi, const float* b1s,
    long long row, bool ok, int rloc)
{
    if (!ok) return;
    float4 bv = ((const float4*)b1s)[rloc];
    float c[16];
    #pragma unroll
    for (int q = 0; q < 4; ++q) {
        float4 v = *(const float4*)(chi + row * 16 + q * 4);
        c[q*4+0] = v.x; c[q*4+1] = v.y; c[q*4+2] = v.z; c[q*4+3] = v.w;
    }
    float o8[16];
    o8[0] = bv.x * c[0];
    #pragma unroll
    for (int m = 1; m < 4; ++m)  o8[m] = bv.y * c[m];
    #pragma unroll
    for (int m = 4; m < 9; ++m)  o8[m] = bv.z * c[m];
    #pragma unroll
    for (int m = 9; m < 16; ++m) o8[m] = bv.w * c[m];
    float4* dst = (float4*)(co + row * 16);
    #pragma unroll
    for (int q = 0; q < 4; ++q)
        dst[q] = make_float4(o8[q*4], o8[q*4+1], o8[q*4+2], o8[q*4+3]);
}

__global__ void __launch_bounds__(NTHR, 2)
ib_mma(const float* __restrict__ x, const float* __restrict__ chi,
       const float* __restrict__ W, const float* __restrict__ b,
       float* __restrict__ a1, float* __restrict__ co,
       long long n, long long T)
{
    extern __shared__ char sm[];
    float* bs = (float*)(sm + SM_BS);
    uint32_t* wt = (uint32_t*)(sm + SM_W);

    const int tid = threadIdx.x, wid = tid >> 5, lane = tid & 31;

    // ---- stage W^T as tf32 (f32 storage), k-permuted storage order, once ----
    // storage t<128: s=t>>3, sub=s&1, sp=s>>1, qc=(t>>1)&3, half=t&1
    //               logical L = 16*sp + 4*qc + 2*sub + half
    // storage t>=128: u=t-128: L = 128 + (u>>1) + 4*(u&1)
    for (int i = tid; i < KBE * KBE; i += NTHR) {
        int nn = i / KBE, t = i - nn * KBE;
        int L;
        if (t < 128) {
            int s = t >> 3;
            L = 16 * (s >> 1) + 4 * ((t >> 1) & 3) + 2 * (s & 1) + (t & 1);
        } else {
            int u = t - 128;
            L = 128 + (u >> 1) + 4 * (u & 1);
        }
        float w = (L < CDIM && nn < CDIM) ? W[L * CDIM + nn] : 0.f;
        wt[nn * WRS + t] = tf(w);
    }
    for (int i = tid; i < KBE; i += NTHR) bs[i] = (i < CDIM) ? b[i] : 0.f;

    // ---- per-warp layout (2M x 2N grid, M=64/warp) ----
    const int mrow = (wid & 1) * 64;
    const int cw   = wid >> 1;
    const int qr = lane >> 2, qc = lane & 3;
    const int g0 = cw ? 9 : 0;

    // B base: group g at wB + g*4352; step s2 at +s2*64 (even) / +s2*64+32 (odd);
    // tail at +512.
    const char* wB = (const char*)wt + ((g0 * 8 + qr) * WRS + 2 * qc) * 4;

    const int grid = gridDim.x;

    // ---- preamble: d_chi for first tile into buf 0 ----
    {
        long long row = blockIdx.x * (long long)TILE + tid;
        stage_dchi(chi, sm, SM_DC, row, (blockIdx.x < T) && (row < n), tid);
    }
    __syncthreads();

    int p = 0;
    for (long long t = blockIdx.x; t < T; t += grid) {
        const long long row0 = t * TILE;
        const float* dc = (const float*)(sm + SM_DC + (uint32_t)p * 4096);
        float* b1s_p = (float*)(sm + SM_B1S + p * 2048);

        // clamped A row pointers (garbage rows are never stored)
        ARow ar;
        #pragma unroll
        for (int f = 0; f < 4; ++f)
            #pragma unroll
            for (int h = 0; h < 2; ++h) {
                long long r = row0 + mrow + f * 16 + h * 8 + qr;
                if (r > n - 1) r = n - 1;
                ar.p[f * 2 + h] = x + r * FDIM + 4 * qc;
            }

        // ---- MMA (single-pass tf32) + a1/b1 epilogue ----
        if (cw == 0)
            compute_tile<0>(ar, dc, wB, bs, b1s_p, a1, row0, n, mrow, qr, qc);
        else
            compute_tile<1>(ar, dc, wB, bs, b1s_p, a1, row0, n, mrow, qr, qc);

        // ---- per-warp: d_chi(t+grid) into buf p^1 (no sync needed) ----
        const long long t2 = t + grid;
        if (t2 < T) {
            long long row2 = t2 * TILE + tid;
            stage_dchi(chi, sm, SM_DC + (uint32_t)(p ^ 1) * 4096, row2, row2 < n, tid);
        }
        __syncthreads();   // b1s[p] + dchi[p^1] ready

        // ---- chi_out(t); overlaps next tile's compute in other warps ----
        chi_out_store(co, chi, b1s_p, row0 + tid, row0 + tid < n, tid);
        p ^= 1;
    }
}

extern "C" void kernel_launch(void* const* d_in, const int* in_sizes, int n_in,
                              void* d_out, int out_size)
{
    int ix = 0, ichi = 1, iW = 3, ib_ = 4;
    long long maxsz = -1;
    for (int i = 0; i < n_in; ++i)
        if ((long long)in_sizes[i] > maxsz) { maxsz = in_sizes[i]; ix = i; }
    long long n = maxsz / FDIM;
    for (int i = 0; i < n_in; ++i) {
        long long s = in_sizes[i];
        if (i == ix) continue;
        if (s == CDIM * CDIM) iW = i;
        else if (s == CDIM)   ib_ = i;
        else if (s == 16 * n) ichi = i;
    }
    const float* x   = (const float*)d_in[ix];
    const float* chi = (const float*)d_in[ichi];
    const float* W   = (const float*)d_in[iW];
    const float* b   = (const float*)d_in[ib_];
    float* a1 = (float*)d_out;
    float* co = a1 + (size_t)n * FDIM;

    long long T = (n + TILE - 1) / TILE;
    int sms = 148;
    cudaDeviceGetAttribute(&sms, cudaDevAttrMultiProcessorCount, 0);
    long long g = 2LL * sms;
    int grid = (int)(T < g ? T : g);

    cudaFuncSetAttribute(ib_mma, cudaFuncAttributeMaxDynamicSharedMemorySize, SMEM_BYTES);
    ib_mma<<<grid, NTHR, SMEM_BYTES>>>(x, chi, W, b, a1, co, n, T);
}

// round 17
// speedup vs baseline: 1.0281x; 1.0281x over previous
#include <cuda_runtime.h>
#include <cstdint>

#define FDIM 128
#define CDIM 132
#define WRS  144          // W smem row stride in floats (conflict-free for LDS.128)
#define TILE 128
#define NTHR 128

// smem byte offsets (per block)
#define SM_BS   0                           // bias: 136 floats
#define SM_B1S  1024                        // b1 double buffer: 2 x 2048
#define SM_DC   5120                        // d_chi double buffer: 2 x 4096 (128 rows x 32B)
#define SM_W    13312                       // W^T tf32 (f32 bits): 136 x 144 x 4 = 78336
#define SMEM_BYTES (SM_W + 136 * WRS * 4)   // 91648 (x2 blocks/SM = 183296)

static __device__ __forceinline__ uint32_t tf(float v) {
    uint32_t r; asm("cvt.rna.tf32.f32 %0, %1;" : "=r"(r) : "f"(v)); return r;
}
static __device__ __forceinline__ void mma_t(float* c, const uint32_t* A,
                                             uint32_t b0, uint32_t b1) {
    asm volatile("mma.sync.aligned.m16n8k8.row.col.f32.tf32.tf32.f32 "
        "{%0,%1,%2,%3}, {%4,%5,%6,%7}, {%8,%9}, {%0,%1,%2,%3};"
        : "+f"(c[0]), "+f"(c[1]), "+f"(c[2]), "+f"(c[3])
        : "r"(A[0]), "r"(A[1]), "r"(A[2]), "r"(A[3]), "r"(b0), "r"(b1));
}

struct ARow { const float* p[8]; };   // boundary tile only: clamped row pointers

// One pair of k8 steps (s2 = 0..7 covers k [16*s2, 16*s2+16)).
// A: one float4 per row-half, natural k order (interior: base + immediate offsets).
// B: one LDS.128 per group (natural W layout, conflict-free).
template<int NG, bool FULL>
static __device__ __forceinline__ void k2step(
    int s2, const float* xb, const ARow& ar, const char* wB, float (*acc)[4])
{
    const int xo = s2 * 16;
    uint32_t A0[4][4], A1[4][4];
    #pragma unroll
    for (int f = 0; f < 4; ++f) {
        float4 v0, v1;
        if (FULL) {
            v0 = *(const float4*)(xb + f * (16 * FDIM) + xo);
            v1 = *(const float4*)(xb + f * (16 * FDIM) + 8 * FDIM + xo);
        } else {
            v0 = *(const float4*)(ar.p[2*f]   + xo);
            v1 = *(const float4*)(ar.p[2*f+1] + xo);
        }
        A0[f][0] = tf(v0.x); A0[f][1] = tf(v1.x);
        A0[f][2] = tf(v0.y); A0[f][3] = tf(v1.y);
        A1[f][0] = tf(v0.z); A1[f][1] = tf(v1.z);
        A1[f][2] = tf(v0.w); A1[f][3] = tf(v1.w);
    }
    #pragma unroll
    for (int g = 0; g < NG; ++g) {
        uint4 bb = *(const uint4*)(wB + g * (8 * WRS * 4) + s2 * 64);
        #pragma unroll
        for (int f = 0; f < 4; ++f)
            mma_t(acc[f * NG + g], A0[f], bb.x, bb.y);
        #pragma unroll
        for (int f = 0; f < 4; ++f)
            mma_t(acc[f * NG + g], A1[f], bb.z, bb.w);
    }
}

template<int CW, bool FULL>
static __device__ __forceinline__ void compute_tile(
    const float* xb, const ARow& ar, const float* dc,
    const char* wB, const char* wBt,
    const float* bs, float* b1s,
    float* __restrict__ a1, long long row0, long long n,
    int mrow, int qr, int qc)
{
    constexpr int NG = CW ? 8 : 9;
    constexpr int G0 = CW ? 9 : 0;

    float acc[4 * NG][4];
    #pragma unroll
    for (int i = 0; i < 4 * NG; ++i)
        #pragma unroll
        for (int j = 0; j < 4; ++j) acc[i][j] = 0.f;

    #pragma unroll
    for (int s2 = 0; s2 < 8; ++s2)
        k2step<NG, FULL>(s2, xb, ar, wB, acc);

    // ---- k8 tail: k = 128..135, A from d_chi smem (natural layout) ----
    {
        uint32_t At[4][4];
        #pragma unroll
        for (int f = 0; f < 4; ++f) {
            int r = mrow + f * 16 + qr;
            float2 u0 = *(const float2*)(dc + r * 8 + 2 * qc);
            float2 u1 = *(const float2*)(dc + (r + 8) * 8 + 2 * qc);
            At[f][0] = tf(u0.x); At[f][1] = tf(u1.x);
            At[f][2] = tf(u0.y); At[f][3] = tf(u1.y);
        }
        #pragma unroll
        for (int g = 0; g < NG; ++g) {
            uint2 bt = *(const uint2*)(wBt + g * (8 * WRS * 4));
            #pragma unroll
            for (int f = 0; f < 4; ++f)
                mma_t(acc[f * NG + g], At[f], bt.x, bt.y);
        }
    }

    // ---- epilogue ----
    #pragma unroll
    for (int f = 0; f < 4; ++f) {
        #pragma unroll
        for (int g = 0; g < NG; ++g) {
            const int ga = G0 + g;
            const float* ac = acc[f * NG + g];
            const int colg = ga * 8 + qc * 2;
            if (ga < 16) {
                float bx = bs[colg], by = bs[colg + 1];
                long long r1 = row0 + mrow + f * 16 + qr;
                if (FULL || r1 < n)
                    *(float2*)(a1 + r1 * FDIM + colg) = make_float2(ac[0] + bx, ac[1] + by);
                if (FULL || r1 + 8 < n)
                    *(float2*)(a1 + (r1 + 8) * FDIM + colg) = make_float2(ac[2] + bx, ac[3] + by);
            } else if (ga == 16) {
                if (qc < 2) {
                    int l = qc * 2;
                    float bx = bs[FDIM + l], by = bs[FDIM + l + 1];
                    int rl = mrow + f * 16 + qr;
                    b1s[rl * 4 + l]       = ac[0] + bx;
                    b1s[rl * 4 + l + 1]   = ac[1] + by;
                    b1s[(rl + 8) * 4 + l]     = ac[2] + bx;
                    b1s[(rl + 8) * 4 + l + 1] = ac[3] + by;
                }
            }
        }
    }
}

// ---- d_chi staging (natural [s0,s1,s2,s3,0,0,0,0]): thread tid = row ----
static __device__ __forceinline__ void stage_dchi(
    const float* __restrict__ chi, char* sm, uint32_t dcoff,
    long long row, bool ok, int rloc)
{
    float c[16];
    #pragma unroll
    for (int q = 0; q < 4; ++q) {
        float4 v = ok ? *(const float4*)(chi + row * 16 + q * 4)
                      : make_float4(0.f, 0.f, 0.f, 0.f);
        c[q*4+0] = v.x; c[q*4+1] = v.y; c[q*4+2] = v.z; c[q*4+3] = v.w;
    }
    float s0 = c[0] * c[0];
    float s1 = c[1]*c[1] + c[2]*c[2] + c[3]*c[3];
    float s2 = 0.f, s3 = 0.f;
    #pragma unroll
    for (int m = 4; m < 9; ++m)  s2 += c[m] * c[m];
    #pragma unroll
    for (int m = 9; m < 16; ++m) s3 += c[m] * c[m];
    float* dc = (float*)(sm + dcoff);
    *(float4*)(dc + rloc * 8)     = make_float4(s0, s1, s2, s3);
    *(float4*)(dc + rloc * 8 + 4) = make_float4(0.f, 0.f, 0.f, 0.f);
}

// ---- chi_out: thread tid = row; reloads chi (L2-warm) ----
static __device__ __forceinline__ void chi_out_store(
    float* __restrict__ co, const float* __restrict__ chi, const float* b1s,
    long long row, bool ok, int rloc)
{
    if (!ok) return;
    float4 bv = ((const float4*)b1s)[rloc];
    float c[16];
    #pragma unroll
    for (int q = 0; q < 4; ++q) {
        float4 v = *(const float4*)(chi + row * 16 + q * 4);
        c[q*4+0] = v.x; c[q*4+1] = v.y; c[q*4+2] = v.z; c[q*4+3] = v.w;
    }
    float o8[16];
    o8[0] = bv.x * c[0];
    #pragma unroll
    for (int m = 1; m < 4; ++m)  o8[m] = bv.y * c[m];
    #pragma unroll
    for (int m = 4; m < 9; ++m)  o8[m] = bv.z * c[m];
    #pragma unroll
    for (int m = 9; m < 16; ++m) o8[m] = bv.w * c[m];
    float4* dst = (float4*)(co + row * 16);
    #pragma unroll
    for (int q = 0; q < 4; ++q)
        dst[q] = make_float4(o8[q*4], o8[q*4+1], o8[q*4+2], o8[q*4+3]);
}

__global__ void __launch_bounds__(NTHR, 2)
ib_mma(const float* __restrict__ x, const float* __restrict__ chi,
       const float* __restrict__ W, const float* __restrict__ b,
       float* __restrict__ a1, float* __restrict__ co,
       long long n, long long T)
{
    extern __shared__ char sm[];
    float* bs = (float*)(sm + SM_BS);
    uint32_t* wt = (uint32_t*)(sm + SM_W);

    const int tid = threadIdx.x, wid = tid >> 5, lane = tid & 31;

    // ---- stage W^T as tf32 bits, NATURAL k order, once ----
    for (int i = tid; i < 136 * 136; i += NTHR) {
        int nn = i / 136, kk = i - (i / 136) * 136;
        float w = (nn < CDIM && kk < CDIM) ? W[kk * CDIM + nn] : 0.f;
        wt[nn * WRS + kk] = tf(w);
    }
    for (int i = tid; i < 136; i += NTHR) bs[i] = (i < CDIM) ? b[i] : 0.f;

    // ---- per-warp layout (2M x 2N grid, M=64/warp) ----
    const int mrow = (wid & 1) * 64;
    const int cw   = wid >> 1;
    const int qr = lane >> 2, qc = lane & 3;
    const int g0 = cw ? 9 : 0;

    const char* wB  = (const char*)wt + (((g0 * 8 + qr) * WRS + 4 * qc)) * 4;
    const char* wBt = (const char*)wt + (((g0 * 8 + qr) * WRS + 128 + 2 * qc)) * 4;

    const int grid = gridDim.x;

    // ---- preamble: d_chi for first tile into buf 0 ----
    {
        long long row = blockIdx.x * (long long)TILE + tid;
        stage_dchi(chi, sm, SM_DC, row, (blockIdx.x < T) && (row < n), tid);
    }
    __syncthreads();

    int p = 0;
    for (long long t = blockIdx.x; t < T; t += grid) {
        const long long row0 = t * TILE;
        const float* dc = (const float*)(sm + SM_DC + (uint32_t)p * 4096);
        float* b1s_p = (float*)(sm + SM_B1S + p * 2048);

        const bool full = (row0 + TILE <= n);
        const float* xb = x + (row0 + mrow + qr) * FDIM + 4 * qc;

        if (full) {
            ARow ar;   // unused
            if (cw == 0)
                compute_tile<0, true>(xb, ar, dc, wB, wBt, bs, b1s_p, a1, row0, n, mrow, qr, qc);
            else
                compute_tile<1, true>(xb, ar, dc, wB, wBt, bs, b1s_p, a1, row0, n, mrow, qr, qc);
        } else {
            ARow ar;
            #pragma unroll
            for (int f = 0; f < 4; ++f)
                #pragma unroll
                for (int h = 0; h < 2; ++h) {
                    long long r = row0 + mrow + f * 16 + h * 8 + qr;
                    if (r > n - 1) r = n - 1;
                    ar.p[f * 2 + h] = x + r * FDIM + 4 * qc;
                }
            if (cw == 0)
                compute_tile<0, false>(xb, ar, dc, wB, wBt, bs, b1s_p, a1, row0, n, mrow, qr, qc);
            else
                compute_tile<1, false>(xb, ar, dc, wB, wBt, bs, b1s_p, a1, row0, n, mrow, qr, qc);
        }

        // ---- per-warp: d_chi(t+grid) into buf p^1 (no sync needed) ----
        const long long t2 = t + grid;
        if (t2 < T) {
            long long row2 = t2 * TILE + tid;
            stage_dchi(chi, sm, SM_DC + (uint32_t)(p ^ 1) * 4096, row2, row2 < n, tid);
        }
        __syncthreads();   // b1s[p] + dchi[p^1] ready

        // ---- chi_out(t); overlaps next tile's compute in other warps ----
        chi_out_store(co, chi, b1s_p, row0 + tid, row0 + tid < n, tid);
        p ^= 1;
    }
}

extern "C" void kernel_launch(void* const* d_in, const int* in_sizes, int n_in,
                              void* d_out, int out_size)
{
    int ix = 0, ichi = 1, iW = 3, ib_ = 4;
    long long maxsz = -1;
    for (int i = 0; i < n_in; ++i)
        if ((long long)in_sizes[i] > maxsz) { maxsz = in_sizes[i]; ix = i; }
    long long n = maxsz / FDIM;
    for (int i = 0; i < n_in; ++i) {
        long long s = in_sizes[i];
        if (i == ix) continue;
        if (s == CDIM * CDIM) iW = i;
        else if (s == CDIM)   ib_ = i;
        else if (s == 16 * n) ichi = i;
    }
    const float* x   = (const float*)d_in[ix];
    const float* chi = (const float*)d_in[ichi];
    const float* W   = (const float*)d_in[iW];
    const float* b   = (const float*)d_in[ib_];
    float* a1 = (float*)d_out;
    float* co = a1 + (size_t)n * FDIM;

    long long T = (n + TILE - 1) / TILE;
    int sms = 148;
    cudaDeviceGetAttribute(&sms, cudaDevAttrMultiProcessorCount, 0);
    long long g = 2LL * sms;
    int grid = (int)(T < g ? T : g);

    cudaFuncSetAttribute(ib_mma, cudaFuncAttributeMaxDynamicSharedMemorySize, SMEM_BYTES);
    ib_mma<<<grid, NTHR, SMEM_BYTES>>>(x, chi, W, b, a1, co, n, T);
}